// round 8
// baseline (speedup 1.0000x reference)
#include <cuda_runtime.h>
#include <cuda_bf16.h>
#include <math.h>

// Problem constants (fixed by setup_inputs)
#define NPTS 32768
#define NV   10475
#define NJ   55
#define KNN  6

// Spatial grid (linear raster ids)
#define GDIM  64
#define NCELL (GDIM * GDIM * GDIM)      // 262144
#define GL    10.0f                     // grid covers [-10, 10]^3
#define GH    0.3125f                   // cell size = 20/64 (exact in fp32)
#define GINV  3.2f                      // 1/GH

typedef unsigned long long u64;
#define KSENT 0xFFFFFFFFFFFFFFFFull

// Scratch (no cudaMalloc allowed).
__device__ int    g_tcnt [NCELL];
__device__ int    g_tstart[NCELL + 1];
__device__ int    g_tcur [NCELL];
__device__ int    g_pcnt [NCELL];
__device__ int    g_pstart[NCELL + 1];
__device__ int    g_pcur [NCELL];
__device__ float4 g_tsorted[NV];         // {x, y, z, orig_template_idx}
__device__ float4 g_psorted[NPTS];       // {x, y, z, orig_point_idx}
__device__ int    g_knn_idx[NPTS * KNN];
__device__ float  g_knn_d  [NPTS * KNN];

// ---------------------------------------------------------------------------
__device__ __forceinline__ int cell_of(float x, float y, float z) {
    int cx = min(GDIM - 1, max(0, (int)((x + GL) * GINV)));
    int cy = min(GDIM - 1, max(0, (int)((y + GL) * GINV)));
    int cz = min(GDIM - 1, max(0, (int)((z + GL) * GINV)));
    return (cz * GDIM + cy) * GDIM + cx;
}

// Exact reference-rounded d2 (verified R3-R7), clamped BEFORE selection,
// packed with the original index into a sortable key.
__device__ __forceinline__ u64 cand_key(float4 t, float px, float py, float pz,
                                        float p2) {
    float t2 = __fadd_rn(__fadd_rn(__fmul_rn(t.x, t.x), __fmul_rn(t.y, t.y)),
                         __fmul_rn(t.z, t.z));
    float cross = __fmaf_rn(pz, t.z, __fmaf_rn(py, t.y, __fmul_rn(px, t.x)));
    float d2 = fmaxf(__fmaf_rn(-2.0f, cross, __fadd_rn(p2, t2)), 0.0f);
    return ((u64)__float_as_uint(d2) << 32) | (u64)__float_as_uint(t.w);
}

__device__ __forceinline__ void key_insert(u64* K, u64 key) {
    if (key < K[KNN - 1]) {
        K[KNN - 1] = key;
#pragma unroll
        for (int k = KNN - 1; k > 0; --k)
            if (K[k] < K[k - 1]) { u64 t = K[k]; K[k] = K[k - 1]; K[k - 1] = t; }
    }
}

// ---------------------------------------------------------------------------
// Prep kernels (fused: templates + points)
// ---------------------------------------------------------------------------
extern "C" __global__ void k_zero() {
    int i = blockIdx.x * blockDim.x + threadIdx.x;
    for (; i < NCELL; i += gridDim.x * blockDim.x) { g_tcnt[i] = 0; g_pcnt[i] = 0; }
}

extern "C" __global__ void k_hist(const float* __restrict__ tpts,
                                  const float* __restrict__ pts) {
    int i = blockIdx.x * blockDim.x + threadIdx.x;
    if (i < NV)
        atomicAdd(&g_tcnt[cell_of(tpts[3*i], tpts[3*i+1], tpts[3*i+2])], 1);
    if (i < NPTS)
        atomicAdd(&g_pcnt[cell_of(pts[3*i], pts[3*i+1], pts[3*i+2])], 1);
}

extern "C" __global__ void __launch_bounds__(1024) k_scan() {
    __shared__ int sA[1024], sB[1024];
    const int t = threadIdx.x;
    const int C = NCELL / 1024;          // 256 cells per thread
#pragma unroll 1
    for (int w = 0; w < 2; ++w) {
        const int* cnt = w ? g_pcnt : g_tcnt;
        int* start = w ? g_pstart : g_tstart;
        int* cur   = w ? g_pcur   : g_tcur;
        int sum = 0;
        for (int i = 0; i < C; ++i) sum += cnt[t * C + i];
        sA[t] = sum; __syncthreads();
        int *src = sA, *dst = sB;
        for (int off = 1; off < 1024; off <<= 1) {
            int v = src[t] + ((t >= off) ? src[t - off] : 0);
            dst[t] = v; __syncthreads();
            int* tmp = src; src = dst; dst = tmp;
        }
        int run = src[t] - sum;          // exclusive base of this chunk
        for (int i = 0; i < C; ++i) {
            int id = t * C + i;
            start[id] = run; cur[id] = run;
            run += cnt[id];
        }
        if (t == 1023) start[NCELL] = run;
        __syncthreads();
    }
}

extern "C" __global__ void k_scatter(const float* __restrict__ tpts,
                                     const float* __restrict__ pts) {
    int i = blockIdx.x * blockDim.x + threadIdx.x;
    if (i < NV) {
        float x = tpts[3*i], y = tpts[3*i+1], z = tpts[3*i+2];
        int pos = atomicAdd(&g_tcur[cell_of(x, y, z)], 1);
        g_tsorted[pos] = make_float4(x, y, z, __uint_as_float((unsigned)i));
    }
    if (i < NPTS) {
        float x = pts[3*i], y = pts[3*i+1], z = pts[3*i+2];
        int pos = atomicAdd(&g_pcur[cell_of(x, y, z)], 1);
        g_psorted[pos] = make_float4(x, y, z, __uint_as_float((unsigned)i));
    }
}

// ---------------------------------------------------------------------------
// Kernel B: warp-uniform grid KNN. Warp = 32 cell-sorted points; box = hull
// of their cells; expand box rings warp-uniformly; broadcast templates from
// smem; per-lane exact keyed top-6; per-lane boundary-distance stop + vote.
// ---------------------------------------------------------------------------
#define SCAN_CELL(c) do {                                                  \
    int s_ = g_tstart[c], e_ = g_tstart[(c) + 1];                          \
    for (int j_ = s_; j_ < e_; ++j_)                                       \
        key_insert(K, cand_key(st[j_], px, py, pz, p2));                   \
} while (0)

extern "C" __global__ void __launch_bounds__(256, 1)
k_knn()
{
    extern __shared__ float4 st[];       // NV float4 = 167600 B

    for (int i = threadIdx.x; i < NV; i += 256) st[i] = g_tsorted[i];
    __syncthreads();

    const int n = blockIdx.x * 256 + threadIdx.x;

    float4 P = g_psorted[n];
    float px = P.x, py = P.y, pz = P.z;
    unsigned pid = __float_as_uint(P.w);
    float p2 = __fadd_rn(__fadd_rn(__fmul_rn(px,px), __fmul_rn(py,py)),
                         __fmul_rn(pz,pz));

    int cx = min(GDIM-1, max(0, (int)((px + GL) * GINV)));
    int cy = min(GDIM-1, max(0, (int)((py + GL) * GINV)));
    int cz = min(GDIM-1, max(0, (int)((pz + GL) * GINV)));

    // Warp hull box of home cells
    int lox = cx, hix = cx, loy = cy, hiy = cy, loz = cz, hiz = cz;
#pragma unroll
    for (int off = 16; off >= 1; off >>= 1) {
        lox = min(lox, __shfl_xor_sync(0xFFFFFFFFu, lox, off));
        hix = max(hix, __shfl_xor_sync(0xFFFFFFFFu, hix, off));
        loy = min(loy, __shfl_xor_sync(0xFFFFFFFFu, loy, off));
        hiy = max(hiy, __shfl_xor_sync(0xFFFFFFFFu, hiy, off));
        loz = min(loz, __shfl_xor_sync(0xFFFFFFFFu, loz, off));
        hiz = max(hiz, __shfl_xor_sync(0xFFFFFFFFu, hiz, off));
    }

    u64 K[KNN];
#pragma unroll
    for (int k = 0; k < KNN; ++k) K[k] = KSENT;

#pragma unroll 1
    for (int r = 0; r < GDIM; ++r) {
        int zlo = loz - r, zhi = hiz + r;
        int z0 = max(zlo, 0), z1 = min(zhi, GDIM - 1);
        for (int zz = z0; zz <= z1; ++zz) {
            bool ze = (zz == zlo) || (zz == zhi);
            int ylo = loy - r, yhi = hiy + r;
            int y0 = max(ylo, 0), y1 = min(yhi, GDIM - 1);
            for (int yy = y0; yy <= y1; ++yy) {
                bool ye = (yy == ylo) || (yy == yhi);
                int cb = (zz * GDIM + yy) * GDIM;
                if (r == 0 || ze || ye) {
                    int x0 = max(lox - r, 0), x1 = min(hix + r, GDIM - 1);
                    for (int xx = x0; xx <= x1; ++xx) SCAN_CELL(cb + xx);
                } else {
                    int xa = lox - r, xb = hix + r;
                    if (xa >= 0)   SCAN_CELL(cb + xa);
                    if (xb < GDIM) SCAN_CELL(cb + xb);
                }
            }
        }
        // Per-lane stop bound: distance from p to scanned-box boundary.
        // Clamped faces -> +inf (no templates outside the grid).
        float dxlo = (lox - r <= 0)        ? 1e30f : px - ((float)(lox - r)     * GH - GL);
        float dxhi = (hix + r >= GDIM - 1) ? 1e30f : ((float)(hix + r + 1) * GH - GL) - px;
        float dylo = (loy - r <= 0)        ? 1e30f : py - ((float)(loy - r)     * GH - GL);
        float dyhi = (hiy + r >= GDIM - 1) ? 1e30f : ((float)(hiy + r + 1) * GH - GL) - py;
        float dzlo = (loz - r <= 0)        ? 1e30f : pz - ((float)(loz - r)     * GH - GL);
        float dzhi = (hiz + r >= GDIM - 1) ? 1e30f : ((float)(hiz + r + 1) * GH - GL) - pz;
        float b = fminf(fminf(fminf(dxlo, dxhi), fminf(dylo, dyhi)),
                        fminf(dzlo, dzhi)) * 0.999f;
        float d6 = __uint_as_float((unsigned)(K[KNN - 1] >> 32));
        bool done = (K[KNN - 1] != KSENT) && (b > 0.0f) && (d6 <= b * b);
        if (__all_sync(0xFFFFFFFFu, done)) break;
    }

#pragma unroll
    for (int k = 0; k < KNN; ++k) {
        g_knn_idx[pid * KNN + k] = (int)(unsigned)(K[k] & 0xFFFFFFFFull);
        g_knn_d  [pid * KNN + k] = __uint_as_float((unsigned)(K[k] >> 32));
    }
}

// ---------------------------------------------------------------------------
// Epilogue (unchanged, measured 17us). One warp = one point.
// ---------------------------------------------------------------------------
extern "C" __global__ void __launch_bounds__(256)
epilogue_kernel(const float* __restrict__ lbs,   // (V,55)
                const float* __restrict__ vt,    // (V,16)
                float* __restrict__ out)         // [N dist | N*16 transform]
{
    int gwarp = (blockIdx.x * blockDim.x + threadIdx.x) >> 5;
    int lane  = threadIdx.x & 31;

    int   idx[KNN];
    float d[KNN];
#pragma unroll
    for (int k = 0; k < KNN; ++k) {
        idx[k] = g_knn_idx[gwarp * KNN + k];
        d[k]   = g_knn_d  [gwarp * KNN + k];
    }

    const float* w0row = lbs + (long)idx[0] * NJ;
    float w0a = w0row[lane];
    float w0b = (lane < NJ - 32) ? w0row[lane + 32] : 0.0f;

    float conf[KNN];
    conf[0] = 1.0f;
#pragma unroll
    for (int k = 1; k < KNN; ++k) {
        const float* wr = lbs + (long)idx[k] * NJ;
        float a = fabsf(wr[lane] - w0a);
        if (lane < NJ - 32) a += fabsf(wr[lane + 32] - w0b);
#pragma unroll
        for (int off = 16; off >= 1; off >>= 1)
            a += __shfl_xor_sync(0xFFFFFFFFu, a, off);
        conf[k] = (expf(-a * (1.0f / 0.02f)) > 0.9f) ? 1.0f : 0.0f;
    }

    float w[KNN];
    float wsum = 0.0f;
#pragma unroll
    for (int k = 0; k < KNN; ++k) {
        w[k] = expf(-d[k]) * conf[k];
        wsum += w[k];
    }
    float inv = 1.0f / wsum;

    float xd  = 0.0f;
    float acc = 0.0f;
#pragma unroll
    for (int k = 0; k < KNN; ++k) {
        float wk = w[k] * inv;
        xd = fmaf(wk, d[k], xd);
        if (lane < 16)
            acc = fmaf(wk, vt[(long)idx[k] * 16 + lane], acc);
    }

    if (lane == 0) out[gwarp] = xd;
    if (lane < 16) out[NPTS + gwarp * 16 + lane] = acc;
}

// ---------------------------------------------------------------------------
// Launch. Inputs: lbs_weights, verts_transform, points, template_points, K.
// ---------------------------------------------------------------------------
extern "C" void kernel_launch(void* const* d_in, const int* in_sizes, int n_in,
                              void* d_out, int out_size)
{
    const float* lbs  = (const float*)d_in[0];
    const float* vt   = (const float*)d_in[1];
    const float* pts  = (const float*)d_in[2];
    const float* tpts = (const float*)d_in[3];
    float* out = (float*)d_out;

    const int smem_bytes = NV * (int)sizeof(float4);   // 167600
    cudaFuncSetAttribute(k_knn,
                         cudaFuncAttributeMaxDynamicSharedMemorySize,
                         smem_bytes);

    k_zero<<<256, 256>>>();
    k_hist<<<(NPTS + 255) / 256, 256>>>(tpts, pts);
    k_scan<<<1, 1024>>>();
    k_scatter<<<(NPTS + 255) / 256, 256>>>(tpts, pts);
    k_knn<<<NPTS / 256, 256, smem_bytes>>>();
    epilogue_kernel<<<(NPTS * 32) / 256, 256>>>(lbs, vt, out);
}

// round 9
// speedup vs baseline: 19.2830x; 19.2830x over previous
#include <cuda_runtime.h>
#include <cuda_bf16.h>
#include <math.h>

// Problem constants (fixed by setup_inputs)
#define NPTS 32768
#define NV   10475
#define NJ   55
#define KNN  6

// 1D x-binning
#define NB    1024
#define BW    0.01953125f        // 20/1024, exact in fp32
#define BINV  51.2f
#define XLIM  10.0f
#define SEPS  1e-3f              // screen slack in s-units (d2 slack 2e-3)
#define DELTA0 0.2f

typedef unsigned long long u64;
#define KSENT 0xFFFFFFFFFFFFFFFFull

// Scratch (no cudaMalloc allowed).
__device__ int    g_tbcnt[NB], g_tbstart[NB + 1], g_tbcur[NB];
__device__ int    g_pbcnt[NB], g_pbstart[NB + 1], g_pbcur[NB];
__device__ float4 g_tsorted[NV + 8];     // {x, y, z, -t2/2}, +8 pad
__device__ int    g_tidx  [NV + 8];      // original template index
__device__ float4 g_psorted[NPTS];       // {x, y, z, orig_point_idx}
__device__ int    g_knn_idx[NPTS * KNN];
__device__ float  g_knn_d  [NPTS * KNN];

__device__ __forceinline__ int bin_of(float x) {
    return min(NB - 1, max(0, (int)((x + XLIM) * BINV)));
}

// Exact reference-rounded d2 (verified R3-R8), clamped BEFORE selection,
// packed with the original index into a scan-order-independent sortable key.
__device__ __forceinline__ u64 cand_key(float4 t, int oidx,
                                        float px, float py, float pz, float p2) {
    float t2 = -2.0f * t.w;              // exact (w = -t2/2 with exact halving)
    float cross = __fmaf_rn(pz, t.z, __fmaf_rn(py, t.y, __fmul_rn(px, t.x)));
    float d2 = fmaxf(__fmaf_rn(-2.0f, cross, __fadd_rn(p2, t2)), 0.0f);
    return ((u64)__float_as_uint(d2) << 32) | (u64)(unsigned)oidx;
}

__device__ __forceinline__ void key_insert(u64* K, u64 key) {
    if (key < K[KNN - 1]) {
        K[KNN - 1] = key;
#pragma unroll
        for (int k = KNN - 1; k > 0; --k)
            if (K[k] < K[k - 1]) { u64 t = K[k]; K[k] = K[k - 1]; K[k - 1] = t; }
    }
}

// ---------------------------------------------------------------------------
// Prep kernels
// ---------------------------------------------------------------------------
extern "C" __global__ void k_zero() {
    int i = blockIdx.x * blockDim.x + threadIdx.x;
    if (i < NB) { g_tbcnt[i] = 0; g_pbcnt[i] = 0; }
}

extern "C" __global__ void k_hist(const float* __restrict__ tpts,
                                  const float* __restrict__ pts) {
    int i = blockIdx.x * blockDim.x + threadIdx.x;
    if (i < NV)   atomicAdd(&g_tbcnt[bin_of(tpts[3 * i])], 1);
    if (i < NPTS) atomicAdd(&g_pbcnt[bin_of(pts [3 * i])], 1);
}

extern "C" __global__ void __launch_bounds__(1024) k_scan() {
    __shared__ int sA[NB], sB[NB];
    const int t = threadIdx.x;
#pragma unroll 1
    for (int w = 0; w < 2; ++w) {
        const int* cnt = w ? g_pbcnt : g_tbcnt;
        int* start = w ? g_pbstart : g_tbstart;
        int* cur   = w ? g_pbcur   : g_tbcur;
        int c = cnt[t];
        sA[t] = c; __syncthreads();
        int *src = sA, *dst = sB;
        for (int off = 1; off < NB; off <<= 1) {
            int v = src[t] + ((t >= off) ? src[t - off] : 0);
            dst[t] = v; __syncthreads();
            int* tmp = src; src = dst; dst = tmp;
        }
        start[t] = src[t] - c; cur[t] = src[t] - c;
        if (t == NB - 1) start[NB] = src[t];
        __syncthreads();
    }
}

extern "C" __global__ void k_scatter(const float* __restrict__ tpts,
                                     const float* __restrict__ pts) {
    int i = blockIdx.x * blockDim.x + threadIdx.x;
    if (i < NV) {
        float x = tpts[3*i], y = tpts[3*i+1], z = tpts[3*i+2];
        float t2 = __fadd_rn(__fadd_rn(__fmul_rn(x, x), __fmul_rn(y, y)),
                             __fmul_rn(z, z));
        int pos = atomicAdd(&g_tbcur[bin_of(x)], 1);
        g_tsorted[pos] = make_float4(x, y, z, -0.5f * t2);
        g_tidx[pos] = i;
    }
    if (i < NV + 8 && i >= NV) {         // pad (overread safety)
        g_tsorted[i] = make_float4(0.f, 0.f, 0.f, -INFINITY);
        g_tidx[i] = 0;
    }
    if (i < NPTS) {
        float x = pts[3*i], y = pts[3*i+1], z = pts[3*i+2];
        int pos = atomicAdd(&g_pbcur[bin_of(x)], 1);
        g_psorted[pos] = make_float4(x, y, z, __uint_as_float((unsigned)i));
    }
}

// ---------------------------------------------------------------------------
// Scan contiguous template segment [s,e) with R4-style screen.
// s_thresh is STALE within each 64-chunk (no loop-carried FP dependency).
// ---------------------------------------------------------------------------
__device__ __forceinline__ void scan_seg(
    const float4* __restrict__ st, const int* __restrict__ stidx,
    int s, int e, float px, float py, float pz, float p2,
    u64* K, float& s_thresh)
{
#pragma unroll 1
    for (int v0 = s; v0 < e; ) {
        const int ce = min(v0 + 64, e);
#pragma unroll 1
        for (; v0 < ce; v0 += 8) {
            float sc[8];
#pragma unroll
            for (int i = 0; i < 8; ++i) {
                float4 t = st[v0 + i];
                float v = fmaf(pz, t.z, fmaf(py, t.y, fmaf(px, t.x, t.w)));
                sc[i] = (v0 + i < ce) ? v : -INFINITY;   // uniform guard
            }
            float m = fmaxf(fmaxf(fmaxf(sc[0], sc[1]), fmaxf(sc[2], sc[3])),
                            fmaxf(fmaxf(sc[4], sc[5]), fmaxf(sc[6], sc[7])));
            if (m > s_thresh) {              // warp-divergent but rare-ish
                unsigned pm = 0;
#pragma unroll
                for (int i = 0; i < 8; ++i)
                    pm |= (sc[i] > s_thresh) ? (1u << i) : 0u;
                while (pm) {
                    int i = __ffs(pm) - 1; pm &= pm - 1;
                    key_insert(K, cand_key(st[v0 + i], stidx[v0 + i],
                                           px, py, pz, p2));
                }
            }
        }
        if (K[KNN - 1] != KSENT) {
            float d6 = __uint_as_float((unsigned)(K[KNN - 1] >> 32));
            // pass screen iff approx d2 < d6 + slack  <=>  s > (p2-d6)/2 - eps
            s_thresh = fmaf(-0.5f, d6, 0.5f * p2) - SEPS;
        }
    }
}

// ---------------------------------------------------------------------------
// Kernel B: windowed KNN. Warp = 32 x-sorted points; contiguous template
// window from shared x-hull; widen (doubling) until 1D bound certifies top-6.
// ---------------------------------------------------------------------------
extern "C" __global__ void __launch_bounds__(256, 1)
k_knn()
{
    extern __shared__ char smem[];
    float4* st    = (float4*)smem;                 // NV+8
    int*    stidx = (int*)(st + NV + 8);           // NV+8
    int*    sbst  = stidx + NV + 8;                // NB+1

    for (int i = threadIdx.x; i < NV + 8; i += 256) {
        st[i] = g_tsorted[i]; stidx[i] = g_tidx[i];
    }
    for (int i = threadIdx.x; i < NB + 1; i += 256) sbst[i] = g_tbstart[i];
    __syncthreads();

    const int n = blockIdx.x * 256 + threadIdx.x;
    float4 P = g_psorted[n];
    float px = P.x, py = P.y, pz = P.z;
    unsigned pid = __float_as_uint(P.w);
    float p2 = __fadd_rn(__fadd_rn(__fmul_rn(px, px), __fmul_rn(py, py)),
                         __fmul_rn(pz, pz));

    // warp x-hull
    float xlo = px, xhi = px;
#pragma unroll
    for (int off = 16; off >= 1; off >>= 1) {
        xlo = fminf(xlo, __shfl_xor_sync(0xFFFFFFFFu, xlo, off));
        xhi = fmaxf(xhi, __shfl_xor_sync(0xFFFFFFFFu, xhi, off));
    }

    u64 K[KNN];
#pragma unroll
    for (int k = 0; k < KNN; ++k) K[k] = KSENT;
    float s_thresh = -INFINITY;

    float delta = DELTA0;
    int blo = bin_of(xlo - delta);
    int bhi = bin_of(xhi + delta);
    scan_seg(st, stidx, sbst[blo], sbst[bhi + 1], px, py, pz, p2, K, s_thresh);

#pragma unroll 1
    for (int it = 0; it < 16; ++it) {
        // 1D certification: unscanned templates have |tx-px| >= bound
        float bxa = (blo == 0)      ? -1e15f : (float)blo       * BW - XLIM;
        float bxb = (bhi == NB - 1) ?  1e15f : (float)(bhi + 1) * BW - XLIM;
        float bound = fminf(px - bxa, bxb - px);
        float d6 = __uint_as_float((unsigned)(K[KNN - 1] >> 32));
        bool done = (K[KNN - 1] != KSENT) &&
                    (d6 <= 0.998f * bound * bound);
        if (__all_sync(0xFFFFFFFFu, done)) break;

        delta *= 2.0f;
        int nblo = bin_of(xlo - delta);
        int nbhi = bin_of(xhi + delta);
        if (nblo < blo)
            scan_seg(st, stidx, sbst[nblo], sbst[blo], px, py, pz, p2, K, s_thresh);
        if (nbhi > bhi)
            scan_seg(st, stidx, sbst[bhi + 1], sbst[nbhi + 1], px, py, pz, p2, K, s_thresh);
        blo = nblo; bhi = nbhi;
    }

#pragma unroll
    for (int k = 0; k < KNN; ++k) {
        g_knn_idx[pid * KNN + k] = (int)(unsigned)(K[k] & 0xFFFFFFFFull);
        g_knn_d  [pid * KNN + k] = __uint_as_float((unsigned)(K[k] >> 32));
    }
}

// ---------------------------------------------------------------------------
// Epilogue (unchanged, measured 17us). One warp = one point.
// ---------------------------------------------------------------------------
extern "C" __global__ void __launch_bounds__(256)
epilogue_kernel(const float* __restrict__ lbs,   // (V,55)
                const float* __restrict__ vt,    // (V,16)
                float* __restrict__ out)         // [N dist | N*16 transform]
{
    int gwarp = (blockIdx.x * blockDim.x + threadIdx.x) >> 5;
    int lane  = threadIdx.x & 31;

    int   idx[KNN];
    float d[KNN];
#pragma unroll
    for (int k = 0; k < KNN; ++k) {
        idx[k] = g_knn_idx[gwarp * KNN + k];
        d[k]   = g_knn_d  [gwarp * KNN + k];
    }

    const float* w0row = lbs + (long)idx[0] * NJ;
    float w0a = w0row[lane];
    float w0b = (lane < NJ - 32) ? w0row[lane + 32] : 0.0f;

    float conf[KNN];
    conf[0] = 1.0f;
#pragma unroll
    for (int k = 1; k < KNN; ++k) {
        const float* wr = lbs + (long)idx[k] * NJ;
        float a = fabsf(wr[lane] - w0a);
        if (lane < NJ - 32) a += fabsf(wr[lane + 32] - w0b);
#pragma unroll
        for (int off = 16; off >= 1; off >>= 1)
            a += __shfl_xor_sync(0xFFFFFFFFu, a, off);
        conf[k] = (expf(-a * (1.0f / 0.02f)) > 0.9f) ? 1.0f : 0.0f;
    }

    float w[KNN];
    float wsum = 0.0f;
#pragma unroll
    for (int k = 0; k < KNN; ++k) {
        w[k] = expf(-d[k]) * conf[k];
        wsum += w[k];
    }
    float inv = 1.0f / wsum;

    float xd  = 0.0f;
    float acc = 0.0f;
#pragma unroll
    for (int k = 0; k < KNN; ++k) {
        float wk = w[k] * inv;
        xd = fmaf(wk, d[k], xd);
        if (lane < 16)
            acc = fmaf(wk, vt[(long)idx[k] * 16 + lane], acc);
    }

    if (lane == 0) out[gwarp] = xd;
    if (lane < 16) out[NPTS + gwarp * 16 + lane] = acc;
}

// ---------------------------------------------------------------------------
// Launch. Inputs: lbs_weights, verts_transform, points, template_points, K.
// ---------------------------------------------------------------------------
extern "C" void kernel_launch(void* const* d_in, const int* in_sizes, int n_in,
                              void* d_out, int out_size)
{
    const float* lbs  = (const float*)d_in[0];
    const float* vt   = (const float*)d_in[1];
    const float* pts  = (const float*)d_in[2];
    const float* tpts = (const float*)d_in[3];
    float* out = (float*)d_out;

    const int smem_bytes = (NV + 8) * 16 + (NV + 8) * 4 + (NB + 1) * 4;
    cudaFuncSetAttribute(k_knn,
                         cudaFuncAttributeMaxDynamicSharedMemorySize,
                         smem_bytes);

    k_zero<<<(NB + 255) / 256, 256>>>();
    k_hist<<<(NPTS + 255) / 256, 256>>>(tpts, pts);
    k_scan<<<1, 1024>>>();
    k_scatter<<<(NPTS + 255) / 256, 256>>>(tpts, pts);
    k_knn<<<NPTS / 256, 256, smem_bytes>>>();
    epilogue_kernel<<<(NPTS * 32) / 256, 256>>>(lbs, vt, out);
}